// round 8
// baseline (speedup 1.0000x reference)
#include <cuda_runtime.h>
#include <cstdint>

#define BATCH 64
#define SEQ   512
#define IDIM  300
#define HID   600
#define GATES 2400
#define NBLK  75          // column-blocks per direction (150 total <= 152 SMs on GB300)
#define NH    8           // hidden units per block
#define NW    32          // gate columns per block (4 gates x 8)
#define NTHR  256
#define KTOT  900
#define KC    100
#define NCH   9
#define CHFL  (KC*BATCH)      // 6400 floats
#define HSLAB (HID*BATCH)     // 38400 floats
#define XSLAB (IDIM*BATCH)    // 19200 floats

// ---------------- device scratch (static; no allocation) ----------------
__device__ __align__(16) float g_xt[2ull*SEQ*XSLAB];   // [dir][t][d*64+b]
__device__ __align__(16) float g_h[2*2*HSLAB];         // [dir][parity][k*64+b]
__device__ int g_bar[2*SEQ];

// ---------------- helpers ----------------
__device__ __forceinline__ float2 ffma2(float2 a, float2 b, float2 c) {
    float2 d;
    asm("fma.rn.f32x2 %0, %1, %2, %3;"
        : "=l"(*(unsigned long long*)&d)
        : "l"(*(unsigned long long*)&a),
          "l"(*(unsigned long long*)&b),
          "l"(*(unsigned long long*)&c));
    return d;
}
__device__ __forceinline__ void cp16(float* smem, const float* g) {
    unsigned s = (unsigned)__cvta_generic_to_shared(smem);
    asm volatile("cp.async.cg.shared.global [%0], [%1], 16;" :: "r"(s), "l"(g));
}
__device__ __forceinline__ void cp_commit() { asm volatile("cp.async.commit_group;"); }
__device__ __forceinline__ void cp_wait1()  { asm volatile("cp.async.wait_group 1;"); }
__device__ __forceinline__ void cp_wait0()  { asm volatile("cp.async.wait_group 0;"); }

__device__ __forceinline__ float sigm(float x) { return 1.0f / (1.0f + __expf(-x)); }
__device__ __forceinline__ float tanh_s(float x) {
    float t = 1.0f - 2.0f / (__expf(2.0f * fabsf(x)) + 1.0f);
    return copysignf(t, x);
}

// ---------------- kernel: reset persistent state (per call) ----------------
__global__ void brnn_reset() {
    int i = blockIdx.x * blockDim.x + threadIdx.x;
    int st = gridDim.x * blockDim.x;
    for (int k = i; k < 2*2*HSLAB; k += st) g_h[k] = 0.0f;
    for (int k = i; k < 2*SEQ;     k += st) g_bar[k] = 0;
}

// ---------------- kernel: transpose x (+ backward-direction gather) ----------------
// g_xt[dir][t][d*64+b] = x[b][ts][d], ts = (dir && t<L_b) ? L_b-1-t : t
__global__ void brnn_xpose(const float* __restrict__ x, const int* __restrict__ len) {
    extern __shared__ float tile[];           // 64 * 301 floats
    __shared__ int L[BATCH];
    const int t = blockIdx.x, dir = blockIdx.y, tid = threadIdx.x;
    if (tid < BATCH) L[tid] = len[tid];
    __syncthreads();
    for (int idx = tid; idx < BATCH*IDIM; idx += NTHR) {
        int b = idx / IDIM, d = idx - b*IDIM;
        int ts = t;
        if (dir) { int l = L[b]; if (t < l) ts = l - 1 - t; }
        tile[b*301 + d] = x[((size_t)b*SEQ + ts)*IDIM + d];
    }
    __syncthreads();
    float* dst = g_xt + ((size_t)dir*SEQ + t)*XSLAB;
    for (int o = tid; o < XSLAB; o += NTHR)
        dst[o] = tile[(o & 63)*301 + (o >> 6)];
}

// ---------------- kernel: persistent bidirectional LSTM ----------------
__global__ void __launch_bounds__(NTHR, 1)
brnn_lstm(const float* __restrict__ Wf, const float* __restrict__ Uf, const float* __restrict__ bf,
          const float* __restrict__ Wb, const float* __restrict__ Ub, const float* __restrict__ bb,
          const int* __restrict__ lengths, float* __restrict__ out)
{
    const int dir = blockIdx.y, blk = blockIdx.x, tid = threadIdx.x;
    const int c0 = blk * NH;

    extern __shared__ float sm[];
    float* Ws  = sm;                 // 900*32 = 28800
    float* As  = Ws  + KTOT*NW;      // 2*6400 = 12800
    float* Zs  = As  + 2*CHFL;       // 64*33  = 2112
    float* Cs  = Zs  + 64*33;        // 512
    float* Acc = Cs  + 512;          // 512
    float* bsm = Acc + 512;          // 32
    int*   lsm = (int*)(bsm + 32);   // 64

    const float* W  = dir ? Wb : Wf;
    const float* U  = dir ? Ub : Uf;
    const float* bd = dir ? bb : bf;

    // one-time setup: weight slice, bias, lengths, state
    for (int idx = tid; idx < KTOT*NW; idx += NTHR) {
        int r = idx >> 5, cc = idx & 31;
        int gc = (cc >> 3)*HID + c0 + (cc & 7);
        Ws[idx] = (r < IDIM) ? W[(size_t)r*GATES + gc]
                             : U[(size_t)(r - IDIM)*GATES + gc];
    }
    if (tid < NW) bsm[tid] = bd[(tid >> 3)*HID + c0 + (tid & 7)];
    if (tid < BATCH) lsm[tid] = lengths[tid];
    for (int idx = tid; idx < 512; idx += NTHR) { Cs[idx] = 0.0f; Acc[idx] = 0.0f; }
    __syncthreads();

    const int tm = tid >> 5, tn = tid & 31;
    const int rowb = tm * 8;
    float* gh = g_h + dir*2*HSLAB;
    const float* gx = g_xt + (size_t)dir*SEQ*XSLAB;
    int* bar = g_bar + dir*SEQ;

    for (int s = 0; s < SEQ; s++) {
        const float* hr = gh + (s & 1)*HSLAB;
        float*       hw = gh + ((s + 1) & 1)*HSLAB;
        const float* xr = gx + (size_t)s*XSLAB;

        float2 a0 = {0.f,0.f}, a1 = {0.f,0.f}, a2 = {0.f,0.f}, a3 = {0.f,0.f};

        // prefetch chunk 0 (x, no dependence on previous step)
        for (int i = tid*4; i < CHFL; i += NTHR*4) cp16(As + i, xr + i);
        cp_commit();

        for (int c = 0; c < NCH; c++) {
            if (c + 1 < NCH) {
                if (c + 1 == 3 && s > 0) {   // h chunks need step s-1 from all blocks
                    if (tid == 0)
                        while (*(volatile int*)&bar[s-1] < NBLK) __nanosleep(40);
                    __syncthreads();
                    __threadfence();         // acquire
                }
                const float* src = (c + 1 < 3) ? xr + (c + 1)*CHFL : hr + (c - 2)*CHFL;
                float* dst = As + ((c + 1) & 1)*CHFL;
                for (int i = tid*4; i < CHFL; i += NTHR*4) cp16(dst + i, src + i);
                cp_commit();
                cp_wait1();
            } else {
                cp_wait0();
            }
            __syncthreads();                 // chunk c visible

            const float* Ab = As + (c & 1)*CHFL;
            const float* Wk = Ws + c*KC*NW + tn;
            #pragma unroll 5
            for (int k = 0; k < KC; k++) {
                const float4 v0 = *(const float4*)(Ab + k*BATCH + rowb);
                const float4 v1 = *(const float4*)(Ab + k*BATCH + rowb + 4);
                const float w = Wk[k*NW];
                const float2 wv = make_float2(w, w);
                a0 = ffma2(make_float2(v0.x, v0.y), wv, a0);
                a1 = ffma2(make_float2(v0.z, v0.w), wv, a1);
                a2 = ffma2(make_float2(v1.x, v1.y), wv, a2);
                a3 = ffma2(make_float2(v1.z, v1.w), wv, a3);
            }
            __syncthreads();                 // all done reading buffer (c&1) before reuse
        }

        // bias + stage z to smem (stride 33 avoids bank conflicts)
        const float bv = bsm[tn];
        Zs[(rowb+0)*33 + tn] = a0.x + bv;  Zs[(rowb+1)*33 + tn] = a0.y + bv;
        Zs[(rowb+2)*33 + tn] = a1.x + bv;  Zs[(rowb+3)*33 + tn] = a1.y + bv;
        Zs[(rowb+4)*33 + tn] = a2.x + bv;  Zs[(rowb+5)*33 + tn] = a2.y + bv;
        Zs[(rowb+6)*33 + tn] = a3.x + bv;  Zs[(rowb+7)*33 + tn] = a3.y + bv;
        __syncthreads();

        // gates: 512 cells (j,b), 2 per thread; cell = j*64+b
        #pragma unroll
        for (int u = 0; u < 2; u++) {
            int cell = tid + u*NTHR;
            int j = cell >> 6, b = cell & 63;
            float zi = Zs[b*33 + j];
            float zf = Zs[b*33 + 8 + j];
            float zg = Zs[b*33 + 16 + j];
            float zo = Zs[b*33 + 24 + j];
            float ig = sigm(zi), fg = sigm(zf), gg = tanh_s(zg), og = sigm(zo);
            float cn = fg * Cs[cell] + ig * gg;
            Cs[cell] = cn;
            float h = og * tanh_s(cn);
            hw[(c0 + j)*BATCH + b] = h;
            if (s < lsm[b]) Acc[cell] += h;
        }
        __syncthreads();
        if (tid == 0) { __threadfence(); atomicAdd(&bar[s], 1); }   // release
    }

    const float inv = 1.0f / (float)SEQ;
    for (int idx = tid; idx < 512; idx += NTHR) {
        int j = idx >> 6, b = idx & 63;
        out[b*1200 + dir*HID + c0 + j] = Acc[idx] * inv;
    }
}

// ---------------- launch ----------------
extern "C" void kernel_launch(void* const* d_in, const int* in_sizes, int n_in,
                              void* d_out, int out_size) {
    (void)in_sizes; (void)out_size;
    const float* x   = (const float*)d_in[0];
    const int*   len = (const int*)d_in[1];
    int base = (n_in >= 9) ? 3 : 2;           // skip scalar 'training' if present
    const float* Wf = (const float*)d_in[base + 0];
    const float* Uf = (const float*)d_in[base + 1];
    const float* bf = (const float*)d_in[base + 2];
    const float* Wb = (const float*)d_in[base + 3];
    const float* Ub = (const float*)d_in[base + 4];
    const float* bb = (const float*)d_in[base + 5];
    float* out = (float*)d_out;

    const int xpose_smem = 64 * 301 * (int)sizeof(float);                 // 77056 B
    const int lstm_smem  = (KTOT*NW + 2*CHFL + 64*33 + 512 + 512 + 32) * (int)sizeof(float)
                         + 64 * (int)sizeof(int);                         // 179328 B
    cudaFuncSetAttribute(brnn_xpose, cudaFuncAttributeMaxDynamicSharedMemorySize, xpose_smem);
    cudaFuncSetAttribute(brnn_lstm,  cudaFuncAttributeMaxDynamicSharedMemorySize, lstm_smem);

    brnn_reset<<<128, 256>>>();
    brnn_xpose<<<dim3(SEQ, 2), NTHR, xpose_smem>>>(x, len);
    brnn_lstm<<<dim3(NBLK, 2), NTHR, lstm_smem>>>(Wf, Uf, bf, Wb, Ub, bb, len, out);
}

// round 11
// speedup vs baseline: 1.5256x; 1.5256x over previous
#include <cuda_runtime.h>
#include <cstdint>

#define BATCH 64
#define SEQ   512
#define IDIM  300
#define HID   600
#define GATES 2400
#define NBLK  75          // column-blocks per direction (150 total; GB300 has 152 SMs)
#define NH    8           // hidden units per block
#define NW    32          // gate columns per block (4 gates x 8)
#define NTHR  256
#define KTOT  900
#define KC    100         // k per chunk
#define KCH   50          // k per warpgroup per chunk
#define NCH   9           // 3 x-chunks then 6 h-chunks
#define NSTG  3           // smem ring stages
#define CHFL  (KC*BATCH)          // 6400 floats
#define CHBYTES (CHFL*4)          // 25600 B
#define HSLAB (HID*BATCH)         // 38400 floats
#define XSLAB (IDIM*BATCH)        // 19200 floats

// ---------------- device scratch (static; no allocation) ----------------
__device__ __align__(16) float g_xt[2ull*SEQ*XSLAB];   // [dir][t][d*64+b]
__device__ __align__(16) float g_h[2*2*HSLAB];         // [dir][parity][k*64+b]
__device__ int g_bar[2*SEQ];

// ---------------- helpers ----------------
__device__ __forceinline__ float2 ffma2(float2 a, float2 b, float2 c) {
    float2 d;
    asm("fma.rn.f32x2 %0, %1, %2, %3;"
        : "=l"(*(unsigned long long*)&d)
        : "l"(*(unsigned long long*)&a),
          "l"(*(unsigned long long*)&b),
          "l"(*(unsigned long long*)&c));
    return d;
}
__device__ __forceinline__ void mbar_init(uint32_t a, uint32_t cnt) {
    asm volatile("mbarrier.init.shared.b64 [%0], %1;" :: "r"(a), "r"(cnt) : "memory");
}
__device__ __forceinline__ void mbar_expect(uint32_t a, uint32_t bytes) {
    asm volatile("mbarrier.arrive.expect_tx.shared.b64 _, [%0], %1;"
                 :: "r"(a), "r"(bytes) : "memory");
}
__device__ __forceinline__ void bulk_g2s(uint32_t dst, const float* src, uint32_t bytes, uint32_t mbar) {
    asm volatile("cp.async.bulk.shared::cluster.global.mbarrier::complete_tx::bytes "
                 "[%0], [%1], %2, [%3];"
                 :: "r"(dst), "l"(src), "r"(bytes), "r"(mbar) : "memory");
}
__device__ __forceinline__ void mbar_wait(uint32_t a, int ph) {
    asm volatile(
        "{\n\t.reg .pred P;\n\t"
        "WL%=:\n\t"
        "mbarrier.try_wait.parity.acquire.cta.shared::cta.b64 P, [%0], %1, 0x989680;\n\t"
        "@P bra WD%=;\n\t"
        "bra WL%=;\n\t"
        "WD%=:\n\t}"
        :: "r"(a), "r"(ph) : "memory");
}
__device__ __forceinline__ float sigm(float x) { return 1.0f / (1.0f + __expf(-x)); }
__device__ __forceinline__ float tanh_s(float x) {
    float t = 1.0f - 2.0f / (__expf(2.0f * fabsf(x)) + 1.0f);
    return copysignf(t, x);
}

// ---------------- kernel: reset persistent state (per call) ----------------
__global__ void brnn_reset() {
    int i = blockIdx.x * blockDim.x + threadIdx.x;
    int st = gridDim.x * blockDim.x;
    for (int k = i; k < 2*2*HSLAB; k += st) g_h[k] = 0.0f;
    for (int k = i; k < 2*SEQ;     k += st) g_bar[k] = 0;
}

// ---------------- kernel: transpose x (+ backward-direction gather) ----------------
// g_xt[dir][t][d*64+b] = x[b][ts][d], ts = (dir && t<L_b) ? L_b-1-t : t
__global__ void brnn_xpose(const float* __restrict__ x, const int* __restrict__ len) {
    extern __shared__ float tile[];           // 64 * 301 floats
    __shared__ int L[BATCH];
    const int t = blockIdx.x, dir = blockIdx.y, tid = threadIdx.x;
    if (tid < BATCH) L[tid] = len[tid];
    __syncthreads();
    for (int idx = tid; idx < BATCH*IDIM; idx += NTHR) {
        int b = idx / IDIM, d = idx - b*IDIM;
        int ts = t;
        if (dir) { int l = L[b]; if (t < l) ts = l - 1 - t; }
        tile[b*301 + d] = x[((size_t)b*SEQ + ts)*IDIM + d];
    }
    __syncthreads();
    float* dst = g_xt + ((size_t)dir*SEQ + t)*XSLAB;
    for (int o = tid; o < XSLAB; o += NTHR)
        dst[o] = tile[(o & 63)*301 + (o >> 6)];
}

// ---------------- kernel: persistent bidirectional LSTM ----------------
__global__ void __launch_bounds__(NTHR, 1)
brnn_lstm(const float* __restrict__ Wf, const float* __restrict__ Uf, const float* __restrict__ bf,
          const float* __restrict__ Wb, const float* __restrict__ Ub, const float* __restrict__ bb,
          const int* __restrict__ lengths, float* __restrict__ out)
{
    const int dir = blockIdx.y, blk = blockIdx.x, tid = threadIdx.x;
    const int c0 = blk * NH;

    extern __shared__ __align__(16) float sm[];
    // [0..16): mbarrier area (3 x u64, 8B aligned)
    float* Ws  = sm + 16;                 // 900*32 = 28800
    float* As  = Ws  + KTOT*NW;           // 3*6400 = 19200 (16B-aligned offset)
    float* Zs  = As  + NSTG*CHFL;         // 64*33  = 2112  (wg0 partial + bias)
    float* Zs2 = Zs  + 64*33;             // 64*33  = 2112  (wg1 partial)
    float* Cs  = Zs2 + 64*33;             // 512
    float* Acc = Cs  + 512;               // 512
    float* bsm = Acc + 512;               // 32
    int*   lsm = (int*)(bsm + 32);        // 64

    const uint32_t smem_base = (uint32_t)__cvta_generic_to_shared(sm);
    const uint32_t mb0 = smem_base;                                  // stage mbarriers
    const uint32_t as0 = smem_base + (16 + KTOT*NW) * 4;             // As stage-0 smem addr

    const float* W  = dir ? Wb : Wf;
    const float* U  = dir ? Ub : Uf;
    const float* bd = dir ? bb : bf;

    // one-time setup: weight slice, bias, lengths, state, mbarriers
    for (int idx = tid; idx < KTOT*NW; idx += NTHR) {
        int r = idx >> 5, cc = idx & 31;
        int gc = (cc >> 3)*HID + c0 + (cc & 7);
        Ws[idx] = (r < IDIM) ? W[(size_t)r*GATES + gc]
                             : U[(size_t)(r - IDIM)*GATES + gc];
    }
    if (tid < NW) bsm[tid] = bd[(tid >> 3)*HID + c0 + (tid & 7)];
    if (tid < BATCH) lsm[tid] = lengths[tid];
    for (int idx = tid; idx < 512; idx += NTHR) { Cs[idx] = 0.0f; Acc[idx] = 0.0f; }
    if (tid == 0) { mbar_init(mb0, 1); mbar_init(mb0 + 8, 1); mbar_init(mb0 + 16, 1); }
    __syncthreads();

    // thread mapping: 2 warpgroups split k; tile = 8 rows x 2 cols
    const int wg   = tid >> 7;            // 0/1
    const int wtid = tid & 127;
    const int rowb = (wtid >> 4) * 8;     // 0,8,...,56
    const int col0 = (wtid & 15) * 2;     // 0,2,...,30

    float* gh = g_h + dir*2*HSLAB;
    const float* gx = g_xt + (size_t)dir*SEQ*XSLAB;
    int* bar = g_bar + dir*SEQ;

    int ph0 = 0, ph1 = 0, ph2 = 0;

    for (int s = 0; s < SEQ; s++) {
        const float* hr = gh + (s & 1)*HSLAB;
        float*       hw = gh + ((s + 1) & 1)*HSLAB;
        const float* xr = gx + (size_t)s*XSLAB;

        // prologue: issue x-chunks 0,1 (independent of previous step)
        if (tid == 0) {
            mbar_expect(mb0, CHBYTES);     bulk_g2s(as0,              xr,        CHBYTES, mb0);
            mbar_expect(mb0 + 8, CHBYTES); bulk_g2s(as0 + CHBYTES,    xr + CHFL, CHBYTES, mb0 + 8);
        }

        float2 a00 = {0.f,0.f}, a01 = {0.f,0.f}, a02 = {0.f,0.f}, a03 = {0.f,0.f};
        float2 a10 = {0.f,0.f}, a11 = {0.f,0.f}, a12 = {0.f,0.f}, a13 = {0.f,0.f};

        for (int c = 0; c < NCH; c++) {
            // h-chunks (c>=3) need step s-1 complete across all blocks of this dir
            if (c == 1 && s > 0) {
                if (tid == 0)
                    while (*(volatile int*)&bar[s-1] < NBLK) __nanosleep(40);
                __syncthreads();
            }
            if (tid == 0 && c + 2 < NCH) {
                const int nc = c + 2;
                const int stg = nc % NSTG;
                const float* src = (nc < 3) ? xr + nc*CHFL : hr + (nc - 3)*CHFL;
                mbar_expect(mb0 + stg*8, CHBYTES);
                bulk_g2s(as0 + stg*CHBYTES, src, CHBYTES, mb0 + stg*8);
            }

            // wait for chunk c's data
            const int stg = c % NSTG;
            int ph = (stg == 0) ? ph0 : (stg == 1) ? ph1 : ph2;
            mbar_wait(mb0 + stg*8, ph);
            if (stg == 0) ph0 ^= 1; else if (stg == 1) ph1 ^= 1; else ph2 ^= 1;

            const float* Ap = As + stg*CHFL + wg*KCH*BATCH + rowb;
            const float* Wp = Ws + (c*KC + wg*KCH)*NW + col0;
            #pragma unroll 10
            for (int k = 0; k < KCH; k++) {
                const float4 v0 = *(const float4*)(Ap + k*BATCH);
                const float4 v1 = *(const float4*)(Ap + k*BATCH + 4);
                const float2 w  = *(const float2*)(Wp + k*NW);
                const float2 w0 = make_float2(w.x, w.x);
                const float2 w1 = make_float2(w.y, w.y);
                a00 = ffma2(make_float2(v0.x, v0.y), w0, a00);
                a01 = ffma2(make_float2(v0.z, v0.w), w0, a01);
                a02 = ffma2(make_float2(v1.x, v1.y), w0, a02);
                a03 = ffma2(make_float2(v1.z, v1.w), w0, a03);
                a10 = ffma2(make_float2(v0.x, v0.y), w1, a10);
                a11 = ffma2(make_float2(v0.z, v0.w), w1, a11);
                a12 = ffma2(make_float2(v1.x, v1.y), w1, a12);
                a13 = ffma2(make_float2(v1.z, v1.w), w1, a13);
            }
            __syncthreads();   // chunk-c buffer free before producer re-arms it
        }

        // stage partials: wg0 -> Zs (+bias), wg1 -> Zs2 (raw)
        {
            float* Zt = wg ? Zs2 : Zs;
            const float ad0 = wg ? 0.f : bsm[col0];
            const float ad1 = wg ? 0.f : bsm[col0 + 1];
            Zt[(rowb+0)*33 + col0] = a00.x + ad0;  Zt[(rowb+1)*33 + col0] = a00.y + ad0;
            Zt[(rowb+2)*33 + col0] = a01.x + ad0;  Zt[(rowb+3)*33 + col0] = a01.y + ad0;
            Zt[(rowb+4)*33 + col0] = a02.x + ad0;  Zt[(rowb+5)*33 + col0] = a02.y + ad0;
            Zt[(rowb+6)*33 + col0] = a03.x + ad0;  Zt[(rowb+7)*33 + col0] = a03.y + ad0;
            Zt[(rowb+0)*33 + col0+1] = a10.x + ad1;  Zt[(rowb+1)*33 + col0+1] = a10.y + ad1;
            Zt[(rowb+2)*33 + col0+1] = a11.x + ad1;  Zt[(rowb+3)*33 + col0+1] = a11.y + ad1;
            Zt[(rowb+4)*33 + col0+1] = a12.x + ad1;  Zt[(rowb+5)*33 + col0+1] = a12.y + ad1;
            Zt[(rowb+6)*33 + col0+1] = a13.x + ad1;  Zt[(rowb+7)*33 + col0+1] = a13.y + ad1;
        }
        __syncthreads();

        // gates: 512 cells (j,b), 2 per thread; cell = j*64+b
        #pragma unroll
        for (int u = 0; u < 2; u++) {
            int cell = tid + u*NTHR;
            int j = cell >> 6, b = cell & 63;
            float zi = Zs[b*33 + j]      + Zs2[b*33 + j];
            float zf = Zs[b*33 + 8 + j]  + Zs2[b*33 + 8 + j];
            float zg = Zs[b*33 + 16 + j] + Zs2[b*33 + 16 + j];
            float zo = Zs[b*33 + 24 + j] + Zs2[b*33 + 24 + j];
            float ig = sigm(zi), fg = sigm(zf), gg = tanh_s(zg), og = sigm(zo);
            float cn = fg * Cs[cell] + ig * gg;
            Cs[cell] = cn;
            float h = og * tanh_s(cn);
            hw[(c0 + j)*BATCH + b] = h;
            if (s < lsm[b]) Acc[cell] += h;
        }
        __threadfence();                 // make h STGs globally visible (all writers)
        __syncthreads();
        if (tid == 0) atomicAdd(&bar[s], 1);   // release step s
    }

    const float inv = 1.0f / (float)SEQ;
    for (int idx = tid; idx < 512; idx += NTHR) {
        int j = idx >> 6, b = idx & 63;
        out[b*1200 + dir*HID + c0 + j] = Acc[idx] * inv;
    }
}

// ---------------- launch ----------------
extern "C" void kernel_launch(void* const* d_in, const int* in_sizes, int n_in,
                              void* d_out, int out_size) {
    (void)in_sizes; (void)out_size;
    const float* x   = (const float*)d_in[0];
    const int*   len = (const int*)d_in[1];
    int base = (n_in >= 9) ? 3 : 2;           // skip scalar 'training' if present
    const float* Wf = (const float*)d_in[base + 0];
    const float* Uf = (const float*)d_in[base + 1];
    const float* bf = (const float*)d_in[base + 2];
    const float* Wb = (const float*)d_in[base + 3];
    const float* Ub = (const float*)d_in[base + 4];
    const float* bb = (const float*)d_in[base + 5];
    float* out = (float*)d_out;

    const int xpose_smem = 64 * 301 * (int)sizeof(float);                 // 77056 B
    const int lstm_smem  = (16 + KTOT*NW + NSTG*CHFL + 2*64*33 + 512 + 512 + 32) * (int)sizeof(float)
                         + 64 * (int)sizeof(int);                          // 213440 B
    cudaFuncSetAttribute(brnn_xpose, cudaFuncAttributeMaxDynamicSharedMemorySize, xpose_smem);
    cudaFuncSetAttribute(brnn_lstm,  cudaFuncAttributeMaxDynamicSharedMemorySize, lstm_smem);

    brnn_reset<<<128, 256>>>();
    brnn_xpose<<<dim3(SEQ, 2), NTHR, xpose_smem>>>(x, len);
    brnn_lstm<<<dim3(NBLK, 2), NTHR, lstm_smem>>>(Wf, Uf, bf, Wb, Ub, bb, len, out);
}